// round 2
// baseline (speedup 1.0000x reference)
#include <cuda_runtime.h>
#include <cstdint>

// ---------------------------------------------------------------------------
// LSTM: T=512, B=64, IN=512, H=1024.
// Phase 1 (parallel): Gx = X @ Wx + b for all t, one big GEMM.
// Phase 2 (persistent kernel, 128 blocks == 1/SM, all co-resident):
//   each block owns 8 H-columns x 4 gates; its 128KB weight slice lives in
//   SMEM for all 512 steps; cell state c lives in SMEM; h chain lives in the
//   output buffer; steps separated by a global arrive+spin barrier.
// Inner loops: packed fma.rn.f32x2 with K-pair-packed accumulators.
// ---------------------------------------------------------------------------

static constexpr int kT  = 512;
static constexpr int kB  = 64;
static constexpr int kIN = 512;
static constexpr int kH  = 1024;
static constexpr int kGXW = 4 * kH;          // 4096
static constexpr int kBH = kB * kH;          // 65536
static constexpr int NBLK = 128;             // persistent grid

typedef unsigned long long ull;

__device__ float g_gx[(size_t)kT * kB * kGXW];   // 512 MB scratch
__device__ unsigned g_bar;                        // global barrier counter

__device__ __forceinline__ void fma2(ull& d, ull a, ull b) {
    asm("fma.rn.f32x2 %0, %1, %2, %0;" : "+l"(d) : "l"(a), "l"(b));
}
__device__ __forceinline__ float redpair(ull v) {
    float2 f = *reinterpret_cast<float2*>(&v);
    return f.x + f.y;
}
__device__ __forceinline__ float sigmoidf_(float x) {
    return 1.0f / (1.0f + __expf(-x));
}

__global__ void reset_kernel() { g_bar = 0u; }

// ---------------------------------------------------------------------------
// Phase 1: Gx = X @ Wx + b.  M=32768, K=512, N=1024 per gate.
// Block 256 thr, tile 128M x 64N (one gate), K-chunk 32, thread 4m x 8n.
// ---------------------------------------------------------------------------
static constexpr int P1_BM = 128;
static constexpr int P1_BN = 64;
static constexpr int P1_BK = 32;

__global__ void __launch_bounds__(256) phase1_kernel(
    const float* __restrict__ x,
    const float* __restrict__ Wf, const float* __restrict__ Wi,
    const float* __restrict__ Wc, const float* __restrict__ Wo,
    const float* __restrict__ bf, const float* __restrict__ bi,
    const float* __restrict__ bc, const float* __restrict__ bo)
{
    __shared__ float As[P1_BM][P1_BK + 4];        // [m][k]
    __shared__ float Bsm[P1_BK / 2][P1_BN * 2];   // k-pair packed

    const int tid  = threadIdx.x;
    const int gate = blockIdx.x >> 4;                  // 0..3
    const int n0   = (blockIdx.x & 15) * P1_BN;        // 0..960
    const int m0   = blockIdx.y * P1_BM;

    const float* W    = (gate == 0) ? Wf : (gate == 1) ? Wi : (gate == 2) ? Wc : Wo;
    const float* bias = (gate == 0) ? bf : (gate == 1) ? bi : (gate == 2) ? bc : bo;

    const int ng = tid & 7;    // cols 8*ng .. 8*ng+7
    const int mg = tid >> 3;   // rows 4*mg .. 4*mg+3

    ull acc[4][8];
#pragma unroll
    for (int i = 0; i < 4; i++)
#pragma unroll
        for (int j = 0; j < 8; j++) acc[i][j] = 0ull;

    float4 pa[4];
    float4 pb0, pb1;

    // prefetch chunk 0
    {
#pragma unroll
        for (int r = 0; r < 4; r++) {
            int idx = tid + r * 256;
            int m = idx >> 3, fk = idx & 7;
            pa[r] = *reinterpret_cast<const float4*>(&x[(size_t)(m0 + m) * kIN + 4 * fk]);
        }
        int kk = tid >> 3, fn = tid & 7;
        const float* wr = &W[(size_t)(kH + kk) * kH + n0 + 8 * fn];
        pb0 = *reinterpret_cast<const float4*>(wr);
        pb1 = *reinterpret_cast<const float4*>(wr + 4);
    }

    const int NCH = kIN / P1_BK;   // 16
    for (int c = 0; c < NCH; ++c) {
        __syncthreads();
#pragma unroll
        for (int r = 0; r < 4; r++) {
            int idx = tid + r * 256;
            int m = idx >> 3, fk = idx & 7;
            *reinterpret_cast<float4*>(&As[m][4 * fk]) = pa[r];
        }
        {
            int kk = tid >> 3, fn = tid & 7;
            float* brow = &Bsm[kk >> 1][0];
            int half = kk & 1;
            int vb = 8 * fn;
            brow[(vb + 0) * 2 + half] = pb0.x;
            brow[(vb + 1) * 2 + half] = pb0.y;
            brow[(vb + 2) * 2 + half] = pb0.z;
            brow[(vb + 3) * 2 + half] = pb0.w;
            brow[(vb + 4) * 2 + half] = pb1.x;
            brow[(vb + 5) * 2 + half] = pb1.y;
            brow[(vb + 6) * 2 + half] = pb1.z;
            brow[(vb + 7) * 2 + half] = pb1.w;
        }
        __syncthreads();
        if (c + 1 < NCH) {
            int kc = (c + 1) * P1_BK;
#pragma unroll
            for (int r = 0; r < 4; r++) {
                int idx = tid + r * 256;
                int m = idx >> 3, fk = idx & 7;
                pa[r] = *reinterpret_cast<const float4*>(&x[(size_t)(m0 + m) * kIN + kc + 4 * fk]);
            }
            int kk = tid >> 3, fn = tid & 7;
            const float* wr = &W[(size_t)(kH + kc + kk) * kH + n0 + 8 * fn];
            pb0 = *reinterpret_cast<const float4*>(wr);
            pb1 = *reinterpret_cast<const float4*>(wr + 4);
        }
#pragma unroll
        for (int k2 = 0; k2 < P1_BK / 2; ++k2) {
            ull a[4];
#pragma unroll
            for (int i = 0; i < 4; i++)
                a[i] = *reinterpret_cast<const ull*>(&As[4 * mg + i][2 * k2]);
            ull b[8];
#pragma unroll
            for (int s = 0; s < 4; s++) {
                float4 q = *reinterpret_cast<const float4*>(&Bsm[k2][16 * ng + 4 * s]);
                b[2 * s + 0] = reinterpret_cast<ull*>(&q)[0];
                b[2 * s + 1] = reinterpret_cast<ull*>(&q)[1];
            }
#pragma unroll
            for (int i = 0; i < 4; i++)
#pragma unroll
                for (int j = 0; j < 8; j++)
                    fma2(acc[i][j], a[i], b[j]);
        }
    }

    float4 bb0 = *reinterpret_cast<const float4*>(&bias[n0 + 8 * ng]);
    float4 bb1 = *reinterpret_cast<const float4*>(&bias[n0 + 8 * ng + 4]);
#pragma unroll
    for (int i = 0; i < 4; i++) {
        int m = m0 + 4 * mg + i;
        float* orow = &g_gx[(size_t)m * kGXW + gate * kH + n0 + 8 * ng];
        float4 o0, o1;
        o0.x = redpair(acc[i][0]) + bb0.x;
        o0.y = redpair(acc[i][1]) + bb0.y;
        o0.z = redpair(acc[i][2]) + bb0.z;
        o0.w = redpair(acc[i][3]) + bb0.w;
        o1.x = redpair(acc[i][4]) + bb1.x;
        o1.y = redpair(acc[i][5]) + bb1.y;
        o1.z = redpair(acc[i][6]) + bb1.z;
        o1.w = redpair(acc[i][7]) + bb1.w;
        *reinterpret_cast<float4*>(orow) = o0;
        *reinterpret_cast<float4*>(orow + 4) = o1;
    }
}

// ---------------------------------------------------------------------------
// Persistent phase-2 kernel. 128 blocks x 256 threads.
// Block bx owns H-cols [8*bx, 8*bx+8) across all 4 gates (32 output cols).
// SMEM: Wres (512 k2 x 64 floats, k-pair packed) = 128KB, h-tile, pre, c.
// ---------------------------------------------------------------------------
static constexpr int S_BK = 32;
static constexpr int SM_W   = 512 * 64;            // 32768 floats
static constexpr int SM_AS  = kB * (S_BK + 4);     // 64*36 = 2304
static constexpr int SM_PRE = kB * 32;             // 2048
static constexpr int SM_C   = kB * 8;              // 512
static constexpr int SM_FLOATS = SM_W + SM_AS + SM_PRE + SM_C;   // 37632
static constexpr int SM_BYTES  = SM_FLOATS * 4;                  // 150528

__global__ void __launch_bounds__(256) lstm_persistent(
    float* __restrict__ out,
    const float* __restrict__ Wf, const float* __restrict__ Wi,
    const float* __restrict__ Wc, const float* __restrict__ Wo)
{
    extern __shared__ float sm[];
    float* Wres  = sm;                 // [k2 global (512)][vn*2+half]
    float* As    = sm + SM_W;          // [64][36]
    float* pre_s = As + SM_AS;         // [64][32]
    float* c_s   = pre_s + SM_PRE;     // [64][8]

    const int tid = threadIdx.x;
    const int bx  = blockIdx.x;
    const int n0h = bx * 8;            // H-column base

    // ---- load resident weight slice (once) ----
    for (int g = 0; g < 4; g++) {
        const float* W = (g == 0) ? Wf : (g == 1) ? Wi : (g == 2) ? Wc : Wo;
        for (int idx = tid; idx < kH * 8; idx += 256) {
            int r = idx >> 3, col = idx & 7;
            float v = W[(size_t)r * kH + n0h + col];
            Wres[(r >> 1) * 64 + (g * 8 + col) * 2 + (r & 1)] = v;
        }
    }
    for (int i = tid; i < SM_C; i += 256) c_s[i] = 0.0f;
    __syncthreads();

    const int txn = tid & 15;   // vn pair group: vn = 2*txn, 2*txn+1
    const int tyb = tid >> 4;   // rows 4*tyb .. 4*tyb+3

    for (int t = 0; t < kT; ++t) {
        // prefetch Gx contributions for this step
        float gxv[4][2];
        {
            const float* gx = g_gx + (size_t)t * kB * kGXW;
#pragma unroll
            for (int i = 0; i < 4; i++) {
                int b = 4 * tyb + i;
#pragma unroll
                for (int j = 0; j < 2; j++) {
                    int vn = 2 * txn + j;
                    gxv[i][j] = gx[(size_t)b * kGXW + (vn >> 3) * kH + n0h + (vn & 7)];
                }
            }
        }

        float pre[4][2];
        if (t == 0) {
#pragma unroll
            for (int i = 0; i < 4; i++) { pre[i][0] = gxv[i][0]; pre[i][1] = gxv[i][1]; }
        } else {
            const float* hprev = out + (size_t)(t - 1) * kBH;
            ull acc[4][2];
#pragma unroll
            for (int i = 0; i < 4; i++) { acc[i][0] = 0ull; acc[i][1] = 0ull; }

            float4 pa[2];
#pragma unroll
            for (int r = 0; r < 2; r++) {
                int idx = tid + r * 256;
                int b = idx >> 3, fk = idx & 7;
                pa[r] = *reinterpret_cast<const float4*>(&hprev[(size_t)b * kH + 4 * fk]);
            }

            const int NCH = kH / S_BK;   // 32
            for (int c = 0; c < NCH; ++c) {
                __syncthreads();
#pragma unroll
                for (int r = 0; r < 2; r++) {
                    int idx = tid + r * 256;
                    int b = idx >> 3, fk = idx & 7;
                    *reinterpret_cast<float4*>(&As[b * (S_BK + 4) + 4 * fk]) = pa[r];
                }
                __syncthreads();
                if (c + 1 < NCH) {
                    int kc = (c + 1) * S_BK;
#pragma unroll
                    for (int r = 0; r < 2; r++) {
                        int idx = tid + r * 256;
                        int b = idx >> 3, fk = idx & 7;
                        pa[r] = *reinterpret_cast<const float4*>(&hprev[(size_t)b * kH + kc + 4 * fk]);
                    }
                }
                const float* wbase = &Wres[(c * 16) * 64];
#pragma unroll
                for (int k2 = 0; k2 < 16; ++k2) {
                    ull a[4];
#pragma unroll
                    for (int i = 0; i < 4; i++)
                        a[i] = *reinterpret_cast<const ull*>(&As[(4 * tyb + i) * (S_BK + 4) + 2 * k2]);
                    float4 bv = *reinterpret_cast<const float4*>(&wbase[k2 * 64 + 4 * txn]);
                    ull b0 = reinterpret_cast<ull*>(&bv)[0];
                    ull b1 = reinterpret_cast<ull*>(&bv)[1];
#pragma unroll
                    for (int i = 0; i < 4; i++) {
                        fma2(acc[i][0], a[i], b0);
                        fma2(acc[i][1], a[i], b1);
                    }
                }
            }
#pragma unroll
            for (int i = 0; i < 4; i++) {
                pre[i][0] = redpair(acc[i][0]) + gxv[i][0];
                pre[i][1] = redpair(acc[i][1]) + gxv[i][1];
            }
        }

        // publish pre-activations
#pragma unroll
        for (int i = 0; i < 4; i++) {
            int b = 4 * tyb + i;
            pre_s[b * 32 + 2 * txn + 0] = pre[i][0];
            pre_s[b * 32 + 2 * txn + 1] = pre[i][1];
        }
        __syncthreads();

        // gate math + c/h update (block owns 64b x 8 cols)
#pragma unroll
        for (int r = 0; r < 2; r++) {
            int idx = tid + r * 256;
            int b = idx >> 3, j = idx & 7;
            float f  = sigmoidf_(pre_s[b * 32 + j]);
            float ii = sigmoidf_(pre_s[b * 32 + 8 + j]);
            float gg = tanhf(pre_s[b * 32 + 16 + j]);
            float oo = sigmoidf_(pre_s[b * 32 + 24 + j]);
            float cn = f * c_s[b * 8 + j] + ii * gg;
            c_s[b * 8 + j] = cn;
            float h = oo * tanhf(cn);
            out[(size_t)t * kBH + (size_t)b * kH + n0h + j] = h;
            if (t == kT - 1) {
                out[(size_t)kT * kBH + (size_t)b * kH + n0h + j] = h;
                out[(size_t)kT * kBH + kBH + (size_t)b * kH + n0h + j] = cn;
            }
        }

        // global barrier between steps
        if (t < kT - 1) {
            __threadfence();
            __syncthreads();
            if (tid == 0) {
                atomicAdd(&g_bar, 1u);
                unsigned target = (unsigned)(t + 1) * NBLK;
                while (*((volatile unsigned*)&g_bar) < target) { __nanosleep(64); }
            }
            __syncthreads();
            __threadfence();
        }
    }
}

// ---------------------------------------------------------------------------
// Launch: reset barrier, phase-1 GEMM, one persistent step kernel.
// ---------------------------------------------------------------------------
extern "C" void kernel_launch(void* const* d_in, const int* in_sizes, int n_in,
                              void* d_out, int out_size)
{
    const float* x  = (const float*)d_in[0];
    const float* Wf = (const float*)d_in[1];
    const float* bf = (const float*)d_in[2];
    const float* Wi = (const float*)d_in[3];
    const float* bi = (const float*)d_in[4];
    const float* Wc = (const float*)d_in[5];
    const float* bc = (const float*)d_in[6];
    const float* Wo = (const float*)d_in[7];
    const float* bo = (const float*)d_in[8];
    float* out = (float*)d_out;

    cudaFuncSetAttribute(lstm_persistent,
                         cudaFuncAttributeMaxDynamicSharedMemorySize, SM_BYTES);

    reset_kernel<<<1, 1>>>();

    dim3 g1(64, kT * kB / P1_BM);   // 64 x 256 blocks
    phase1_kernel<<<g1, 256>>>(x, Wf, Wi, Wc, Wo, bf, bi, bc, bo);

    lstm_persistent<<<NBLK, 256, SM_BYTES>>>(out, Wf, Wi, Wc, Wo);
}